// round 10
// baseline (speedup 1.0000x reference)
#include <cuda_runtime.h>
#include <cstdint>

#define BATCH 8
#define LSEQ  2048
#define DCH   256
#define NST   64

// ---- device scratch (static: no dynamic allocation allowed) ----
__device__ float gA[NST * NST];
__device__ float gAinv[NST * NST];
__device__ float gdt[DCH];
__device__ float gDA[DCH * NST * NST];
__device__ float gWT[DCH * DCH];                 // W_out transposed [din][dout]
__device__ float gKpad[(LSEQ + 32) * DCH];       // 32 zero rows then k[l][d]
__device__ float gY[BATCH * LSEQ * DCH];

typedef unsigned long long u64t;

__device__ __forceinline__ float softplusf(float x) {
    return (x > 20.0f) ? x : log1pf(expf(x));
}

__device__ __forceinline__ float red8(float v) {
    v += __shfl_down_sync(0xffffffffu, v, 4);
    v += __shfl_down_sync(0xffffffffu, v, 2);
    v += __shfl_down_sync(0xffffffffu, v, 1);
    return v;
}

__device__ __forceinline__ u64t pk2(float lo, float hi) {
    u64t r;
    asm("mov.b64 %0, {%1, %2};" : "=l"(r)
        : "r"(__float_as_uint(lo)), "r"(__float_as_uint(hi)));
    return r;
}
__device__ __forceinline__ u64t ffma2(u64t a, u64t b, u64t c) {
    u64t d;
    asm("fma.rn.f32x2 %0, %1, %2, %3;" : "=l"(d) : "l"(a), "l"(b), "l"(c));
    return d;
}
__device__ __forceinline__ void upk2(u64t v, float& lo, float& hi) {
    unsigned a, b;
    asm("mov.b64 {%0, %1}, %2;" : "=r"(a), "=r"(b) : "l"(v));
    lo = __uint_as_float(a);
    hi = __uint_as_float(b);
}

// ---- dual-layout 64x64 matmul: C = A @ B. 512 threads. ----
// A read from stride-65 copy (row scalar, conflict-free).
// B read from stride-68 copy via 2 broadcast LDS.128 per j (16B aligned).
// Output written to BOTH layouts (C65 stride 65, C68 stride 68).
__device__ void mm64d(const float* __restrict__ A65, const float* __restrict__ B68,
                      float* __restrict__ C65, float* __restrict__ C68) {
    __syncthreads();
    int n = threadIdx.x & 63;
    int g = threadIdx.x >> 6;   // 0..7 -> columns [8g, 8g+8)
    float a0 = 0.f, a1 = 0.f, a2 = 0.f, a3 = 0.f, a4 = 0.f, a5 = 0.f, a6 = 0.f, a7 = 0.f;
    for (int j = 0; j < 64; ++j) {
        float a = A65[n * 65 + j];
        const float4* b4 = (const float4*)(B68 + j * 68 + g * 8);
        float4 b0 = b4[0];
        float4 b1 = b4[1];
        a0 = fmaf(a, b0.x, a0); a1 = fmaf(a, b0.y, a1);
        a2 = fmaf(a, b0.z, a2); a3 = fmaf(a, b0.w, a3);
        a4 = fmaf(a, b1.x, a4); a5 = fmaf(a, b1.y, a5);
        a6 = fmaf(a, b1.z, a6); a7 = fmaf(a, b1.w, a7);
    }
    float* c65 = C65 + n * 65 + g * 8;
    c65[0] = a0; c65[1] = a1; c65[2] = a2; c65[3] = a3;
    c65[4] = a4; c65[5] = a5; c65[6] = a6; c65[7] = a7;
    float4* c68 = (float4*)(C68 + n * 68 + g * 8);
    c68[0] = make_float4(a0, a1, a2, a3);
    c68[1] = make_float4(a4, a5, a6, a7);
    __syncthreads();
}

// ---- K0: A=softplus(log_A); dt; Ainv=(A+1e-6 I)^-1 (Gauss-Jordan, pivoted) ----
__global__ void k0_prep(const float* __restrict__ log_A,
                        const float* __restrict__ log_delta) {
    __shared__ float Ms[64][130];
    __shared__ float fs[64];
    __shared__ int piv_s;
    int tid = threadIdx.x;

    for (int idx = tid; idx < 64 * 64; idx += 256) {
        int n = idx >> 6, m = idx & 63;
        float a = softplusf(log_A[idx]);
        gA[idx] = a;
        Ms[n][m] = a + ((n == m) ? 1e-6f : 0.0f);
        Ms[n][64 + m] = (n == m) ? 1.0f : 0.0f;
    }
    gdt[tid] = softplusf(log_delta[tid]) + 1e-6f;
    __syncthreads();

    for (int p = 0; p < 64; ++p) {
        if (tid == 0) {
            int best = p; float bv = fabsf(Ms[p][p]);
            for (int r = p + 1; r < 64; ++r) {
                float v = fabsf(Ms[r][p]);
                if (v > bv) { bv = v; best = r; }
            }
            piv_s = best;
        }
        __syncthreads();
        int pr = piv_s;
        if (pr != p) {
            for (int c = tid; c < 128; c += 256) {
                float t = Ms[p][c]; Ms[p][c] = Ms[pr][c]; Ms[pr][c] = t;
            }
        }
        __syncthreads();
        float inv = 1.0f / Ms[p][p];
        __syncthreads();
        for (int c = tid; c < 128; c += 256) Ms[p][c] *= inv;
        __syncthreads();
        if (tid < 64) fs[tid] = Ms[tid][p];
        __syncthreads();
        for (int idx = tid; idx < 64 * 128; idx += 256) {
            int i = idx >> 7, c = idx & 127;
            if (i != p) Ms[i][c] -= fs[i] * Ms[p][c];
        }
        __syncthreads();
    }
    for (int idx = tid; idx < 64 * 64; idx += 256) {
        int n = idx >> 6, m = idx & 63;
        gAinv[idx] = Ms[n][64 + m];
    }
}

// ---- K0b: transpose W_out ----
__global__ void k0b_wt(const float* __restrict__ W) {
    int r = blockIdx.x, c = threadIdx.x;
    gWT[c * 256 + r] = W[r * 256 + c];
}

// ---- K1: dA_d = expm(dt_d * A). One block (512 thr) per d. ----
// smem layout (floats): Ts65[0], P65[4160], P68[8320], Q65[12672], Q68[16832]
#define K1_P65 4160
#define K1_P68 8320
#define K1_Q65 12672
#define K1_Q68 16832
#define K1_SMEM ((16832 + 64 * 68) * 4)
__global__ void k1_expm() {
    extern __shared__ float sm[];
    float* Ts  = sm;
    float* P65 = sm + K1_P65;
    float* P68 = sm + K1_P68;
    float* Q65 = sm + K1_Q65;
    float* Q68 = sm + K1_Q68;
    __shared__ float colsum[64];
    __shared__ int s_scal, s_K;
    int tid = threadIdx.x;
    int d = blockIdx.x;
    float dt = gdt[d];

    for (int idx = tid; idx < 64 * 64; idx += 512) {
        int n = idx >> 6, m = idx & 63;
        Ts[n * 65 + m] = gA[idx] * dt;
    }
    __syncthreads();
    if (tid < 64) {
        float s = 0.0f;
        for (int n = 0; n < 64; ++n) s += fabsf(Ts[n * 65 + tid]);
        colsum[tid] = s;
    }
    __syncthreads();
    if (tid == 0) {
        float mx = 0.0f;
        for (int m = 0; m < 64; ++m) mx = fmaxf(mx, colsum[m]);
        int sc = 0; float nn = mx;
        while (nn > 0.5f) { nn *= 0.5f; sc++; }
        int K;
        if      (nn < 7e-3f)  K = 3;
        else if (nn < 0.026f) K = 4;
        else if (nn < 0.065f) K = 5;
        else if (nn < 0.126f) K = 6;
        else if (nn < 0.212f) K = 7;
        else if (nn < 0.32f)  K = 8;
        else if (nn < 0.45f)  K = 9;
        else                  K = 10;
        s_scal = sc; s_K = K;
    }
    __syncthreads();
    int sc = s_scal, K = s_K;
    if (sc > 0) {
        float f = ldexpf(1.0f, -sc);
        for (int idx = tid; idx < 64 * 64; idx += 512) {
            int n = idx >> 6, m = idx & 63;
            Ts[n * 65 + m] *= f;
        }
        __syncthreads();
    }
    {   // P = I + T/K  (both layouts)
        float invK = 1.0f / (float)K;
        for (int idx = tid; idx < 64 * 64; idx += 512) {
            int n = idx >> 6, m = idx & 63;
            float v = ((n == m) ? 1.0f : 0.0f) + Ts[n * 65 + m] * invK;
            P65[n * 65 + m] = v;
            P68[n * 68 + m] = v;
        }
    }
    for (int kk = K - 1; kk >= 1; --kk) {  // Q = T*P ; P = I + Q/kk
        mm64d(Ts, P68, Q65, Q68);
        float invk = 1.0f / (float)kk;
        for (int idx = tid; idx < 64 * 64; idx += 512) {
            int n = idx >> 6, m = idx & 63;
            float v = ((n == m) ? 1.0f : 0.0f) + Q65[n * 65 + m] * invk;
            P65[n * 65 + m] = v;
            P68[n * 68 + m] = v;
        }
        __syncthreads();
    }
    for (int q = 0; q < sc; ++q) {
        mm64d(P65, P68, Q65, Q68);
        for (int idx = tid; idx < 64 * 64; idx += 512) {
            int n = idx >> 6, m = idx & 63;
            float v = Q65[n * 65 + m];
            P65[n * 65 + m] = v;
            P68[n * 68 + m] = v;
        }
        __syncthreads();
    }
    for (int idx = tid; idx < 64 * 64; idx += 512) {
        int n = idx >> 6, m = idx & 63;
        gDA[(size_t)d * 4096 + idx] = P65[n * 65 + m];
    }
}

// ---- K2: build kpad. k[64j+i] = u_i . v_j ; u_i=(dA^T)^i C ; v_{j+1}=dA^64 v_j ----
// smem (floats): dA65[0] dA68[4160] P65[8512] P68[12672] Q65[17024] Q68[21184]
//                Us[25536] (64x65)  Vs[29696] (64x33)
#define K2_DA68 4160
#define K2_P65  8512
#define K2_P68  12672
#define K2_Q65  17024
#define K2_Q68  21184
#define K2_US   25536
#define K2_VS   29696
#define K2_SMEM ((29696 + 64 * 33) * 4)
__global__ void k2_kernelgen(const float* __restrict__ Bp,
                             const float* __restrict__ Cp) {
    extern __shared__ float sm[];
    float* dA65 = sm;
    float* dA68 = sm + K2_DA68;
    float* P65  = sm + K2_P65;
    float* P68  = sm + K2_P68;
    float* Q65  = sm + K2_Q65;   // initially stages Ainv (row reads only)
    float* Q68  = sm + K2_Q68;
    float* Us   = sm + K2_US;    // Us[i*65+n] : u_i
    float* Vs   = sm + K2_VS;    // Vs[n*33+j] : v_j
    __shared__ float bvec[64], xs[64], dBv[64];
    int tid = threadIdx.x;
    int d = blockIdx.x;
    int n8 = tid >> 3, p8 = tid & 7;

    for (int idx = tid; idx < 64 * 64; idx += 512) {
        int n = idx >> 6, m = idx & 63;
        float v = gDA[(size_t)d * 4096 + idx];
        dA65[n * 65 + m] = v;
        dA68[n * 68 + m] = v;
        Q65[n * 65 + m]  = gAinv[idx];
    }
    if (tid < 64) bvec[tid] = Bp[d * 64 + tid];
    if (tid < 32) gKpad[tid * 256 + d] = 0.0f;
    __syncthreads();

    { // xs = Ainv * Bp[d]   (Ainv staged in Q65)
        float s = 0.0f;
#pragma unroll
        for (int q = 0; q < 8; ++q)
            s = fmaf(Q65[n8 * 65 + p8 * 8 + q], bvec[p8 * 8 + q], s);
        s = red8(s);
        if (p8 == 0) xs[n8] = s;
    }
    __syncthreads();
    { // dBv = (dA - I) xs
        float s = 0.0f;
#pragma unroll
        for (int q = 0; q < 8; ++q)
            s = fmaf(dA65[n8 * 65 + p8 * 8 + q], xs[p8 * 8 + q], s);
        s = red8(s);
        if (p8 == 0) dBv[n8] = s - xs[n8];
    }
    if (tid < 64) Us[tid] = Cp[d * 64 + tid];  // u_0
    __syncthreads();
    for (int i = 1; i < 64; ++i) {             // u_i = dA^T u_{i-1}
        float s = 0.0f;
#pragma unroll
        for (int q = 0; q < 8; ++q)
            s = fmaf(dA65[(p8 * 8 + q) * 65 + n8], Us[(i - 1) * 65 + p8 * 8 + q], s);
        s = red8(s);
        if (p8 == 0) Us[i * 65 + n8] = s;
        __syncthreads();
    }
    // P = dA^64 (6 squarings, ping-pong Q/P; Ainv in Q65 is dead now)
    mm64d(dA65, dA68, Q65, Q68);
    mm64d(Q65, Q68, P65, P68);
    mm64d(P65, P68, Q65, Q68);
    mm64d(Q65, Q68, P65, P68);
    mm64d(P65, P68, Q65, Q68);
    mm64d(Q65, Q68, P65, P68);

    if (tid < 64) Vs[tid * 33 + 0] = dBv[tid];
    __syncthreads();
    for (int j = 1; j < 32; ++j) {             // v_j = P v_{j-1}
        float s = 0.0f;
#pragma unroll
        for (int q = 0; q < 8; ++q)
            s = fmaf(P65[n8 * 65 + p8 * 8 + q], Vs[(p8 * 8 + q) * 33 + (j - 1)], s);
        s = red8(s);
        if (p8 == 0) Vs[n8 * 33 + j] = s;
        __syncthreads();
    }
    // k tile: k[64j+i] = sum_n Us[i][n] Vs[n][j]; 2048 outputs, 4/thread
    {
        int i  = tid >> 3;
        int j0 = (tid & 7) * 4;
        float s0 = 0.0f, s1 = 0.0f, s2 = 0.0f, s3 = 0.0f;
        for (int n = 0; n < 64; ++n) {
            float uv = Us[i * 65 + n];
            s0 = fmaf(uv, Vs[n * 33 + j0 + 0], s0);
            s1 = fmaf(uv, Vs[n * 33 + j0 + 1], s1);
            s2 = fmaf(uv, Vs[n * 33 + j0 + 2], s2);
            s3 = fmaf(uv, Vs[n * 33 + j0 + 3], s3);
        }
        gKpad[(size_t)(32 + (j0 + 0) * 64 + i) * 256 + d] = s0;
        gKpad[(size_t)(32 + (j0 + 1) * 64 + i) * 256 + d] = s1;
        gKpad[(size_t)(32 + (j0 + 2) * 64 + i) * 256 + d] = s2;
        gKpad[(size_t)(32 + (j0 + 3) * 64 + i) * 256 + d] = s3;
    }
}

// ---- K3: causal conv, f32x2 packed FMA. thread = channel d. ----
// acc2[i] = output pair (t0+i, t0+i+16); weight pair (k[w],k[w+16]) with
// w = 32+i-u. u-loop split in halves so only 31 pairs are live at once
// (w in [1,31] for u in [16,31]; w in [17,47] for u in [0,15]) -> 2 blocks/SM.
__global__ void __launch_bounds__(256, 2) k3_conv(const float* __restrict__ x) {
    int bx = blockIdx.x;
    int tile = 63 - (bx >> 3);   // heavy (triangular) tiles launch first
    int b = bx & 7;
    int d = threadIdx.x;
    int t0 = tile * 32;
    const float* xb = x + (size_t)b * LSEQ * DCH + d;
    u64t acc2[16];
#pragma unroll
    for (int i = 0; i < 16; ++i) acc2[i] = 0ull;

    for (int c = 0; c <= tile; ++c) {
        int base = t0 - c * 32;
        const float* kp = gKpad + (size_t)base * DCH + d;
        const float* xp = xb + (size_t)c * 32 * DCH;
        {   // half A: u in [16,31], pairs w in [1,31] -> pq[w-1]
            u64t pq[31];
#pragma unroll
            for (int w = 1; w <= 31; ++w)
                pq[w - 1] = pk2(kp[(size_t)w * DCH], kp[(size_t)(w + 16) * DCH]);
#pragma unroll
            for (int u = 16; u < 32; ++u) {
                float xv = xp[(size_t)u * DCH];
                u64t xv2 = pk2(xv, xv);
#pragma unroll
                for (int i = 0; i < 16; ++i)
                    acc2[i] = ffma2(pq[31 + i - u], xv2, acc2[i]);
            }
        }
        {   // half B: u in [0,15], pairs w in [17,47] -> pq[w-17]
            u64t pq[31];
#pragma unroll
            for (int w = 17; w <= 47; ++w)
                pq[w - 17] = pk2(kp[(size_t)w * DCH], kp[(size_t)(w + 16) * DCH]);
#pragma unroll
            for (int u = 0; u < 16; ++u) {
                float xv = xp[(size_t)u * DCH];
                u64t xv2 = pk2(xv, xv);
#pragma unroll
                for (int i = 0; i < 16; ++i)
                    acc2[i] = ffma2(pq[15 + i - u], xv2, acc2[i]);
            }
        }
    }
    float* yo = gY + ((size_t)b * LSEQ + t0) * DCH + d;
#pragma unroll
    for (int i = 0; i < 16; ++i) {
        float lo, hi;
        upk2(acc2[i], lo, hi);
        yo[(size_t)i * DCH]        = lo;
        yo[(size_t)(i + 16) * DCH] = hi;
    }
}

// ---- K4: out = (y + x*skip) @ W^T + b, f32x2 + LDS.128 z-loads. ----
__global__ void __launch_bounds__(256, 2) k4_out(const float* __restrict__ x,
        const float* __restrict__ skip_D, const float* __restrict__ b_out,
        float* __restrict__ out) {
    __shared__ __align__(16) float zs[32][256];
    int row0 = blockIdx.x * 32;
    int tid = threadIdx.x;
    for (int idx = tid; idx < 32 * 256; idx += 256) {
        int r = idx >> 8, dd = idx & 255;
        size_t g = (size_t)(row0 + r) * 256 + dd;
        zs[r][dd] = gY[g] + x[g] * skip_D[dd];
    }
    __syncthreads();
    u64t acc2[32];
#pragma unroll
    for (int r = 0; r < 32; ++r) acc2[r] = 0ull;
    for (int kk = 0; kk < 256; kk += 4) {
        float wa = gWT[(kk + 0) * 256 + tid];
        float wb = gWT[(kk + 1) * 256 + tid];
        float wc = gWT[(kk + 2) * 256 + tid];
        float wd = gWT[(kk + 3) * 256 + tid];
        u64t w01 = pk2(wa, wb);
        u64t w23 = pk2(wc, wd);
#pragma unroll
        for (int r = 0; r < 32; ++r) {
            ulonglong2 zz = *(const ulonglong2*)&zs[r][kk];  // one LDS.128
            acc2[r] = ffma2(zz.x, w01, acc2[r]);
            acc2[r] = ffma2(zz.y, w23, acc2[r]);
        }
    }
    float bo = b_out[tid];
#pragma unroll
    for (int r = 0; r < 32; ++r) {
        float lo, hi;
        upk2(acc2[r], lo, hi);
        out[(size_t)(row0 + r) * 256 + tid] = lo + hi + bo;
    }
}

extern "C" void kernel_launch(void* const* d_in, const int* in_sizes, int n_in,
                              void* d_out, int out_size) {
    const float* x         = (const float*)d_in[0];
    const float* log_A     = (const float*)d_in[1];
    const float* Bp        = (const float*)d_in[2];
    const float* Cp        = (const float*)d_in[3];
    const float* log_delta = (const float*)d_in[4];
    const float* skip_D    = (const float*)d_in[5];
    const float* W_out     = (const float*)d_in[6];
    const float* b_out     = (const float*)d_in[7];
    float* out = (float*)d_out;

    cudaFuncSetAttribute(k1_expm, cudaFuncAttributeMaxDynamicSharedMemorySize, K1_SMEM);
    cudaFuncSetAttribute(k2_kernelgen, cudaFuncAttributeMaxDynamicSharedMemorySize, K2_SMEM);

    k0_prep<<<1, 256>>>(log_A, log_delta);
    k0b_wt<<<256, 256>>>(W_out);
    k1_expm<<<256, 512, K1_SMEM>>>();
    k2_kernelgen<<<256, 512, K2_SMEM>>>(Bp, Cp);
    k3_conv<<<512, 256>>>(x);
    k4_out<<<512, 256>>>(x, skip_D, b_out, out);
}

// round 15
// speedup vs baseline: 1.0119x; 1.0119x over previous
#include <cuda_runtime.h>
#include <cstdint>

#define BATCH 8
#define LSEQ  2048
#define DCH   256
#define NST   64

// ---- device scratch (static) ----
__device__ float gA[NST * NST];
__device__ float gAinv[NST * NST];
__device__ float gdt[DCH];
__device__ float gDA[DCH * NST * NST];
__device__ float gWT[DCH * DCH];                  // W_out^T [din][dout]
__device__ float gU[DCH * NST * NST];             // U[d][i][n]  (u_i = (dA^T)^i C)
__device__ float gP[DCH * NST * NST];             // P[d][n][q]  (dA^64)
__device__ float gG[DCH * NST * NST];             // G[d][n][t]  (dA^{64-t} dB)[n]
__device__ float gK64[DCH * NST];                 // k[d][0..63]
__device__ float gXT[DCH * BATCH * LSEQ];         // x transposed [d][b*L+t]
__device__ float gY[BATCH * LSEQ * DCH];

typedef unsigned long long u64t;

__device__ __forceinline__ float softplusf(float x) {
    return (x > 20.0f) ? x : log1pf(expf(x));
}
__device__ __forceinline__ float red8(float v) {
    v += __shfl_down_sync(0xffffffffu, v, 4);
    v += __shfl_down_sync(0xffffffffu, v, 2);
    v += __shfl_down_sync(0xffffffffu, v, 1);
    return v;
}
__device__ __forceinline__ u64t pk2(float lo, float hi) {
    u64t r;
    asm("mov.b64 %0, {%1, %2};" : "=l"(r)
        : "r"(__float_as_uint(lo)), "r"(__float_as_uint(hi)));
    return r;
}
__device__ __forceinline__ u64t ffma2(u64t a, u64t b, u64t c) {
    u64t d;
    asm("fma.rn.f32x2 %0, %1, %2, %3;" : "=l"(d) : "l"(a), "l"(b), "l"(c));
    return d;
}
__device__ __forceinline__ void upk2(u64t v, float& lo, float& hi) {
    unsigned a, b;
    asm("mov.b64 {%0, %1}, %2;" : "=r"(a), "=r"(b) : "l"(v));
    lo = __uint_as_float(a);
    hi = __uint_as_float(b);
}

// C = A @ B, 64x64 stride-65 smem tiles, 512 threads. Leading+trailing syncs.
__device__ void mm64(const float* __restrict__ A, const float* __restrict__ B,
                     float* __restrict__ C) {
    __syncthreads();
    int n = threadIdx.x & 63;
    int g = threadIdx.x >> 6;   // 0..7
    float acc[8];
#pragma unroll
    for (int q = 0; q < 8; ++q) acc[q] = 0.0f;
    for (int j = 0; j < 64; ++j) {
        float a = A[n * 65 + j];
#pragma unroll
        for (int q = 0; q < 8; ++q)
            acc[q] = fmaf(a, B[j * 65 + g * 8 + q], acc[q]);
    }
#pragma unroll
    for (int q = 0; q < 8; ++q) C[n * 65 + g * 8 + q] = acc[q];
    __syncthreads();
}

// Doubling step: given power M = dA^m (stride-65), extend
//   U rows: u_{r+m}[n] = sum_q M[q][n] * u_r[q]   (transposed apply)
//   H rows: h_{(r+1)+m} = M @ h_{r+1}             (slot r -> slot r+m)
__device__ void double_UH(const float* __restrict__ M, float* __restrict__ Us,
                          float* __restrict__ Hs, int m) {
    for (int o = threadIdx.x; o < m * 64; o += 512) {
        int r = o >> 6, n = o & 63;
        float su = 0.0f, sh = 0.0f;
        for (int q = 0; q < 64; ++q) {
            su = fmaf(M[q * 65 + n], Us[r * 65 + q], su);  // column read (conflict-free)
            sh = fmaf(M[n * 65 + q], Hs[r * 65 + q], sh);  // row read (conflict-free)
        }
        Us[(r + m) * 65 + n] = su;
        Hs[(r + m) * 65 + n] = sh;
    }
    __syncthreads();
}

// ---- K0: A=softplus(log_A); dt; Ainv=(A+1e-6 I)^-1 ----
__global__ void k0_prep(const float* __restrict__ log_A,
                        const float* __restrict__ log_delta) {
    __shared__ float Ms[64][130];
    __shared__ float fs[64];
    __shared__ int piv_s;
    int tid = threadIdx.x;

    for (int idx = tid; idx < 64 * 64; idx += 256) {
        int n = idx >> 6, m = idx & 63;
        float a = softplusf(log_A[idx]);
        gA[idx] = a;
        Ms[n][m] = a + ((n == m) ? 1e-6f : 0.0f);
        Ms[n][64 + m] = (n == m) ? 1.0f : 0.0f;
    }
    gdt[tid] = softplusf(log_delta[tid]) + 1e-6f;
    __syncthreads();

    for (int p = 0; p < 64; ++p) {
        if (tid == 0) {
            int best = p; float bv = fabsf(Ms[p][p]);
            for (int r = p + 1; r < 64; ++r) {
                float v = fabsf(Ms[r][p]);
                if (v > bv) { bv = v; best = r; }
            }
            piv_s = best;
        }
        __syncthreads();
        int pr = piv_s;
        if (pr != p) {
            for (int c = tid; c < 128; c += 256) {
                float t = Ms[p][c]; Ms[p][c] = Ms[pr][c]; Ms[pr][c] = t;
            }
        }
        __syncthreads();
        float inv = 1.0f / Ms[p][p];
        __syncthreads();
        for (int c = tid; c < 128; c += 256) Ms[p][c] *= inv;
        __syncthreads();
        if (tid < 64) fs[tid] = Ms[tid][p];
        __syncthreads();
        for (int idx = tid; idx < 64 * 128; idx += 256) {
            int i = idx >> 7, c = idx & 127;
            if (i != p) Ms[i][c] -= fs[i] * Ms[p][c];
        }
        __syncthreads();
    }
    for (int idx = tid; idx < 64 * 64; idx += 256) {
        int n = idx >> 6, m = idx & 63;
        gAinv[idx] = Ms[n][64 + m];
    }
}

// ---- K0b: transpose W_out ----
__global__ void k0b_wt(const float* __restrict__ W) {
    int r = blockIdx.x, c = threadIdx.x;
    gWT[c * 256 + r] = W[r * 256 + c];
}

// ---- Kxt: transpose x -> gXT[d][b*L+t] ----
__global__ void k_xt(const float* __restrict__ x) {
    __shared__ float ts[32][33];
    int b = blockIdx.z;
    int t0 = blockIdx.x * 32;
    int d0 = blockIdx.y * 32;
    int tx = threadIdx.x & 31, ty = threadIdx.x >> 5;   // 32x8
    for (int r = ty; r < 32; r += 8)
        ts[r][tx] = x[((size_t)b * LSEQ + t0 + r) * DCH + d0 + tx];
    __syncthreads();
    for (int r = ty; r < 32; r += 8)
        gXT[(size_t)(d0 + r) * (BATCH * LSEQ) + (size_t)b * LSEQ + t0 + tx] = ts[tx][r];
}

// ---- K1: dA_d = expm(dt_d * A). One block (512 thr) per d. ----
__global__ void k1_expm() {
    extern __shared__ float sm[];
    float* Ts = sm;
    float* Ps = sm + 64 * 65;
    float* Qs = sm + 2 * 64 * 65;
    __shared__ float colsum[64];
    __shared__ int s_scal, s_K;
    int tid = threadIdx.x;
    int d = blockIdx.x;
    float dt = gdt[d];

    for (int idx = tid; idx < 64 * 64; idx += 512) {
        int n = idx >> 6, m = idx & 63;
        Ts[n * 65 + m] = gA[idx] * dt;
    }
    __syncthreads();
    if (tid < 64) {
        float s = 0.0f;
        for (int n = 0; n < 64; ++n) s += fabsf(Ts[n * 65 + tid]);
        colsum[tid] = s;
    }
    __syncthreads();
    if (tid == 0) {
        float mx = 0.0f;
        for (int m = 0; m < 64; ++m) mx = fmaxf(mx, colsum[m]);
        int sc = 0; float nn = mx;
        while (nn > 0.5f) { nn *= 0.5f; sc++; }
        int K;
        if      (nn < 7e-3f)  K = 3;
        else if (nn < 0.026f) K = 4;
        else if (nn < 0.065f) K = 5;
        else if (nn < 0.126f) K = 6;
        else if (nn < 0.212f) K = 7;
        else if (nn < 0.32f)  K = 8;
        else if (nn < 0.45f)  K = 9;
        else                  K = 10;
        s_scal = sc; s_K = K;
    }
    __syncthreads();
    int sc = s_scal, K = s_K;
    if (sc > 0) {
        float f = ldexpf(1.0f, -sc);
        for (int idx = tid; idx < 64 * 64; idx += 512) {
            int n = idx >> 6, m = idx & 63;
            Ts[n * 65 + m] *= f;
        }
        __syncthreads();
    }
    {   // P = I + T/K
        float invK = 1.0f / (float)K;
        for (int idx = tid; idx < 64 * 64; idx += 512) {
            int n = idx >> 6, m = idx & 63;
            Ps[n * 65 + m] = ((n == m) ? 1.0f : 0.0f) + Ts[n * 65 + m] * invK;
        }
    }
    for (int kk = K - 1; kk >= 1; --kk) {
        mm64(Ts, Ps, Qs);
        float invk = 1.0f / (float)kk;
        for (int idx = tid; idx < 64 * 64; idx += 512) {
            int n = idx >> 6, m = idx & 63;
            Ps[n * 65 + m] = ((n == m) ? 1.0f : 0.0f) + Qs[n * 65 + m] * invk;
        }
    }
    for (int q = 0; q < sc; ++q) {
        mm64(Ps, Ps, Qs);
        for (int idx = tid; idx < 64 * 64; idx += 512) {
            int n = idx >> 6, m = idx & 63;
            Ps[n * 65 + m] = Qs[n * 65 + m];
        }
    }
    __syncthreads();
    for (int idx = tid; idx < 64 * 64; idx += 512) {
        int n = idx >> 6, m = idx & 63;
        gDA[(size_t)d * 4096 + idx] = Ps[n * 65 + m];
    }
}

// ---- K2: per d build U (64 rows), P=dA^64, G, k64 via log-doubling. ----
// smem floats: dAs[0] Ps[4160] Qs[8320] Us[12480] Hs[16640]; total 20800 fl.
#define K2_SMEM (20800 * 4)
__global__ void k2_gen(const float* __restrict__ Bp, const float* __restrict__ Cp) {
    extern __shared__ float sm[];
    float* dAs = sm;
    float* Ps  = sm + 4160;
    float* Qs  = sm + 8320;   // stages Ainv first
    float* Us  = sm + 12480;  // u_r at Us[r*65+n]
    float* Hs  = sm + 16640;  // h_j (=dA^j dBv) at Hs[(j-1)*65+n]
    __shared__ float bvec[64], xs[64], dBv[64], k64s[64];
    int tid = threadIdx.x;
    int d = blockIdx.x;
    int n8 = tid >> 3, p8 = tid & 7;

    for (int idx = tid; idx < 64 * 64; idx += 512) {
        int n = idx >> 6, m = idx & 63;
        dAs[n * 65 + m] = gDA[(size_t)d * 4096 + idx];
        Qs[n * 65 + m]  = gAinv[idx];
    }
    if (tid < 64) bvec[tid] = Bp[d * 64 + tid];
    __syncthreads();

    { // xs = Ainv * Bp[d]
        float s = 0.0f;
#pragma unroll
        for (int q = 0; q < 8; ++q)
            s = fmaf(Qs[n8 * 65 + p8 * 8 + q], bvec[p8 * 8 + q], s);
        s = red8(s);
        if (p8 == 0) xs[n8] = s;
    }
    __syncthreads();
    { // dBv = (dA - I) xs
        float s = 0.0f;
#pragma unroll
        for (int q = 0; q < 8; ++q)
            s = fmaf(dAs[n8 * 65 + p8 * 8 + q], xs[p8 * 8 + q], s);
        s = red8(s);
        if (p8 == 0) dBv[n8] = s - xs[n8];
    }
    if (tid < 64) Us[tid] = Cp[d * 64 + tid];  // u_0 = C
    __syncthreads();
    { // h_1 = dA * dBv
        float s = 0.0f;
#pragma unroll
        for (int q = 0; q < 8; ++q)
            s = fmaf(dAs[n8 * 65 + p8 * 8 + q], dBv[p8 * 8 + q], s);
        s = red8(s);
        if (p8 == 0) Hs[n8] = s;
    }
    __syncthreads();

    // log-doubling interleaved with squarings
    double_UH(dAs, Us, Hs, 1);     // uses dA^1
    mm64(dAs, dAs, Ps);            // S2
    double_UH(Ps, Us, Hs, 2);
    mm64(Ps, Ps, Qs);              // S4 (Ainv dead)
    double_UH(Qs, Us, Hs, 4);
    mm64(Qs, Qs, Ps);              // S8
    double_UH(Ps, Us, Hs, 8);
    mm64(Ps, Ps, Qs);              // S16
    double_UH(Qs, Us, Hs, 16);
    mm64(Qs, Qs, Ps);              // S32
    double_UH(Ps, Us, Hs, 32);
    mm64(Ps, Ps, Qs);              // S64 = P  (in Qs)

    { // k64[tau] = u_tau . dBv
        float s = 0.0f;
#pragma unroll
        for (int q = 0; q < 8; ++q)
            s = fmaf(Us[n8 * 65 + p8 * 8 + q], dBv[p8 * 8 + q], s);
        s = red8(s);
        if (p8 == 0) k64s[n8] = s;
    }
    __syncthreads();

    for (int idx = tid; idx < 4096; idx += 512) {
        int i = idx >> 6, q = idx & 63;
        gU[(size_t)d * 4096 + idx] = Us[i * 65 + q];
        gP[(size_t)d * 4096 + idx] = Qs[i * 65 + q];
        gG[(size_t)d * 4096 + idx] = Hs[(63 - q) * 65 + i];  // G[i][t]=h_{64-t}[i]
    }
    if (tid < 64) gK64[d * 64 + tid] = k64s[tid];
}

// ---- K3: chunked SSM scan. Block = d; 512 thr = (b 8) x (i 64). ----
// y[64j+i] = K_loc[i][:].x_ch + u_i.s_j ;  s_{j+1}[i] = P[i][:].s_j + G[i][:].x_ch
// smem: U68/P68/G68/K68 (64x68 each), xsm[8][68], ssm[2][8][68]
#define K3_SMEM ((4 * 64 * 68 + 8 * 68 + 2 * 8 * 68) * 4)
__global__ void __launch_bounds__(512, 2) k3_ssm() {
    extern __shared__ __align__(16) float sm[];
    float* U68 = sm;
    float* P68 = sm + 64 * 68;
    float* G68 = sm + 2 * 64 * 68;
    float* K68 = sm + 3 * 64 * 68;
    float* xsm = sm + 4 * 64 * 68;            // [8][68]
    float* ssm = sm + 4 * 64 * 68 + 8 * 68;   // [2][8][68]
    __shared__ float k64s[64];
    int tid = threadIdx.x;
    int d = blockIdx.x;
    int b = tid >> 6, i = tid & 63;

    for (int idx = tid; idx < 4096; idx += 512) {
        int r = idx >> 6, c = idx & 63;
        U68[r * 68 + c] = gU[(size_t)d * 4096 + idx];
        P68[r * 68 + c] = gP[(size_t)d * 4096 + idx];
        G68[r * 68 + c] = gG[(size_t)d * 4096 + idx];
    }
    if (tid < 64) k64s[tid] = gK64[d * 64 + tid];
    ssm[b * 68 + i] = 0.0f;                   // s_0 = 0 (par 0)
    __syncthreads();
    for (int idx = tid; idx < 4096; idx += 512) {
        int r = idx >> 6, c = idx & 63;       // K[i=r][t=c] = k64[r-c] if c<=r
        K68[r * 68 + c] = (c <= r) ? k64s[r - c] : 0.0f;
    }
    const float* xcol = gXT + (size_t)d * (BATCH * LSEQ) + (size_t)b * LSEQ;
    __syncthreads();

    int par = 0;
    for (int j = 0; j < 32; ++j) {
        xsm[b * 68 + i] = xcol[j * 64 + i];
        __syncthreads();
        const float* srow = ssm + par * 8 * 68 + b * 68;
        const float* xrow = xsm + b * 68;
        const float* urow = U68 + i * 68;
        const float* prow = P68 + i * 68;
        const float* grow = G68 + i * 68;
        const float* krow = K68 + i * 68;
        u64t yacc = 0ull, sacc = 0ull;
#pragma unroll
        for (int c = 0; c < 16; ++c) {
            ulonglong2 sv = *(const ulonglong2*)(srow + 4 * c);
            ulonglong2 uv = *(const ulonglong2*)(urow + 4 * c);
            ulonglong2 pv = *(const ulonglong2*)(prow + 4 * c);
            yacc = ffma2(uv.x, sv.x, yacc);
            yacc = ffma2(uv.y, sv.y, yacc);
            sacc = ffma2(pv.x, sv.x, sacc);
            sacc = ffma2(pv.y, sv.y, sacc);
            ulonglong2 xv = *(const ulonglong2*)(xrow + 4 * c);
            ulonglong2 gv = *(const ulonglong2*)(grow + 4 * c);
            ulonglong2 kv = *(const ulonglong2*)(krow + 4 * c);
            sacc = ffma2(gv.x, xv.x, sacc);
            sacc = ffma2(gv.y, xv.y, sacc);
            yacc = ffma2(kv.x, xv.x, yacc);
            yacc = ffma2(kv.y, xv.y, yacc);
        }
        float ylo, yhi, slo, shi;
        upk2(yacc, ylo, yhi);
        upk2(sacc, slo, shi);
        ssm[(1 - par) * 8 * 68 + b * 68 + i] = slo + shi;
        gY[((size_t)b * LSEQ + j * 64 + i) * DCH + d] = ylo + yhi;
        __syncthreads();
        par ^= 1;
    }
}

// ---- K4: out = (y + x*skip) @ W^T + b ----
__global__ void __launch_bounds__(256, 2) k4_out(const float* __restrict__ x,
        const float* __restrict__ skip_D, const float* __restrict__ b_out,
        float* __restrict__ out) {
    __shared__ __align__(16) float zs[32][256];
    int row0 = blockIdx.x * 32;
    int tid = threadIdx.x;
    for (int idx = tid; idx < 32 * 256; idx += 256) {
        int r = idx >> 8, dd = idx & 255;
        size_t g = (size_t)(row0 + r) * 256 + dd;
        zs[r][dd] = gY[g] + x[g] * skip_D[dd];
    }
    __syncthreads();
    u64t acc2[32];
#pragma unroll
    for (int r = 0; r < 32; ++r) acc2[r] = 0ull;
    for (int kk = 0; kk < 256; kk += 4) {
        float wa = gWT[(kk + 0) * 256 + tid];
        float wb = gWT[(kk + 1) * 256 + tid];
        float wc = gWT[(kk + 2) * 256 + tid];
        float wd = gWT[(kk + 3) * 256 + tid];
        u64t w01 = pk2(wa, wb);
        u64t w23 = pk2(wc, wd);
#pragma unroll
        for (int r = 0; r < 32; ++r) {
            ulonglong2 zz = *(const ulonglong2*)&zs[r][kk];
            acc2[r] = ffma2(zz.x, w01, acc2[r]);
            acc2[r] = ffma2(zz.y, w23, acc2[r]);
        }
    }
    float bo = b_out[tid];
#pragma unroll
    for (int r = 0; r < 32; ++r) {
        float lo, hi;
        upk2(acc2[r], lo, hi);
        out[(size_t)(row0 + r) * 256 + tid] = lo + hi + bo;
    }
}

extern "C" void kernel_launch(void* const* d_in, const int* in_sizes, int n_in,
                              void* d_out, int out_size) {
    const float* x         = (const float*)d_in[0];
    const float* log_A     = (const float*)d_in[1];
    const float* Bp        = (const float*)d_in[2];
    const float* Cp        = (const float*)d_in[3];
    const float* log_delta = (const float*)d_in[4];
    const float* skip_D    = (const float*)d_in[5];
    const float* W_out     = (const float*)d_in[6];
    const float* b_out     = (const float*)d_in[7];
    float* out = (float*)d_out;

    const int shm1 = 3 * 64 * 65 * (int)sizeof(float);
    cudaFuncSetAttribute(k1_expm, cudaFuncAttributeMaxDynamicSharedMemorySize, shm1);
    cudaFuncSetAttribute(k2_gen, cudaFuncAttributeMaxDynamicSharedMemorySize, K2_SMEM);
    cudaFuncSetAttribute(k3_ssm, cudaFuncAttributeMaxDynamicSharedMemorySize, K3_SMEM);

    k0_prep<<<1, 256>>>(log_A, log_delta);
    k0b_wt<<<256, 256>>>(W_out);
    k_xt<<<dim3(LSEQ / 32, DCH / 32, BATCH), 256>>>(x);
    k1_expm<<<256, 512, shm1>>>();
    k2_gen<<<256, 512, K2_SMEM>>>(Bp, Cp);
    k3_ssm<<<256, 512, K3_SMEM>>>();
    k4_out<<<512, 256>>>(x, skip_D, b_out, out);
}